// round 1
// baseline (speedup 1.0000x reference)
#include <cuda_runtime.h>
#include <math.h>

#define BATCH  4
#define SEQ    2048
#define DMODEL 1024
#define NHEAD  16
#define DK     64
#define BL     (BATCH * SEQ)          // 8192
#define SCALE  (1.0f / 32.0f)         // 1/sqrt(DMODEL)
#define LN_EPS 1e-3f
#define SPAD   68

// Scratch (allocation-free rule: __device__ globals)
__device__ float g_Q[NHEAD * BL * DK];     // [h][b][l][dk]
__device__ float g_K[NHEAD * BL * DK];
__device__ float g_V[NHEAD * BL * DK];
__device__ float g_O[BL * DMODEL];         // [b][l][h*64+dv] concat layout
__device__ float g_P[BL * DMODEL];         // proj + bias + residual

// ---------------------------------------------------------------------------
// Kernel 1: QKV projection GEMM.  X[8192,1024] @ W[h][1024,64] -> [h][8192,64]
// grid: (128 row-tiles, 16 heads, 3 matrices), 256 threads, 64x64 tile, 4x4 micro
// ---------------------------------------------------------------------------
__global__ __launch_bounds__(256) void qkv_gemm_kernel(
    const float* __restrict__ X,
    const float* __restrict__ Wq,
    const float* __restrict__ Wk,
    const float* __restrict__ Wv)
{
    const float* W;
    float* Out;
    if (blockIdx.z == 0)      { W = Wq; Out = g_Q; }
    else if (blockIdx.z == 1) { W = Wk; Out = g_K; }
    else                      { W = Wv; Out = g_V; }
    W   += (size_t)blockIdx.y * DMODEL * DK;
    Out += (size_t)blockIdx.y * BL * DK;
    const int row0 = blockIdx.x * 64;

    __shared__ float Ast[16][SPAD];   // Ast[k][row]
    __shared__ float Bs[16][SPAD];    // Bs[k][n]

    const int tid = threadIdx.x;
    const int tx = tid & 15, ty = tid >> 4;
    const int ar = tid >> 2, ak = (tid & 3) << 2;   // A-load: row, 4 k's
    const int bk = tid >> 4, bn = (tid & 15) << 2;  // B-load: k, 4 n's

    float acc[4][4] = {};

    for (int k0 = 0; k0 < DMODEL; k0 += 16) {
        float4 av = *(const float4*)&X[(size_t)(row0 + ar) * DMODEL + k0 + ak];
        Ast[ak + 0][ar] = av.x; Ast[ak + 1][ar] = av.y;
        Ast[ak + 2][ar] = av.z; Ast[ak + 3][ar] = av.w;
        float4 bv = *(const float4*)&W[(size_t)(k0 + bk) * DK + bn];
        *(float4*)&Bs[bk][bn] = bv;
        __syncthreads();
        #pragma unroll
        for (int kk = 0; kk < 16; kk++) {
            float4 a = *(float4*)&Ast[kk][ty * 4];
            float4 b = *(float4*)&Bs[kk][tx * 4];
            acc[0][0] += a.x * b.x; acc[0][1] += a.x * b.y; acc[0][2] += a.x * b.z; acc[0][3] += a.x * b.w;
            acc[1][0] += a.y * b.x; acc[1][1] += a.y * b.y; acc[1][2] += a.y * b.z; acc[1][3] += a.y * b.w;
            acc[2][0] += a.z * b.x; acc[2][1] += a.z * b.y; acc[2][2] += a.z * b.z; acc[2][3] += a.z * b.w;
            acc[3][0] += a.w * b.x; acc[3][1] += a.w * b.y; acc[3][2] += a.w * b.z; acc[3][3] += a.w * b.w;
        }
        __syncthreads();
    }
    #pragma unroll
    for (int i = 0; i < 4; i++)
        #pragma unroll
        for (int j = 0; j < 4; j++)
            Out[(size_t)(row0 + ty * 4 + i) * DK + tx * 4 + j] = acc[i][j];
}

// ---------------------------------------------------------------------------
// Kernel 2: Flash attention.  Per (head, batch): Q,K,V [2048,64].
// grid: (32 q-tiles, 64 head*batch), 256 threads, BQ=BK=64, 4x4 micro.
// Ps aliases Kst smem.  Out written in concat layout [b][l][h*64+dv].
// ---------------------------------------------------------------------------
__global__ __launch_bounds__(256) void attn_kernel()
{
    extern __shared__ float sm[];
    float* Qst = sm;                   // Qst[d][r], pre-scaled by 1/32
    float* KPs = sm + 64 * SPAD;       // Kst[d][c]  aliased with  Ps[r][k]
    float* Vs  = sm + 2 * 64 * SPAD;   // Vs[k][c]

    const int tid = threadIdx.x;
    const int tx = tid & 15, ty = tid >> 4;
    const int h = blockIdx.y >> 2, b = blockIdx.y & 3;
    const size_t base = (size_t)(h * BATCH + b) * SEQ * DK;
    const float* Qg = g_Q + base;
    const float* Kg = g_K + base;
    const float* Vg = g_V + base;
    const int q0 = blockIdx.x * 64;

    // Load Q tile transposed, fold in 1/32 scale
    for (int e = tid; e < 1024; e += 256) {
        int r = e >> 4, dd = (e & 15) << 2;
        float4 v = *(const float4*)&Qg[(size_t)(q0 + r) * DK + dd];
        Qst[(dd + 0) * SPAD + r] = v.x * SCALE;
        Qst[(dd + 1) * SPAD + r] = v.y * SCALE;
        Qst[(dd + 2) * SPAD + r] = v.z * SCALE;
        Qst[(dd + 3) * SPAD + r] = v.w * SCALE;
    }

    float m_i[4], l_i[4], acc[4][4];
    #pragma unroll
    for (int i = 0; i < 4; i++) {
        m_i[i] = -1e30f; l_i[i] = 0.f;
        #pragma unroll
        for (int j = 0; j < 4; j++) acc[i][j] = 0.f;
    }
    __syncthreads();

    for (int kv0 = 0; kv0 < SEQ; kv0 += 64) {
        // Load K (transposed) and V tiles
        for (int e = tid; e < 1024; e += 256) {
            int r = e >> 4, dd = (e & 15) << 2;
            float4 kv = *(const float4*)&Kg[(size_t)(kv0 + r) * DK + dd];
            KPs[(dd + 0) * SPAD + r] = kv.x;
            KPs[(dd + 1) * SPAD + r] = kv.y;
            KPs[(dd + 2) * SPAD + r] = kv.z;
            KPs[(dd + 3) * SPAD + r] = kv.w;
            float4 vv = *(const float4*)&Vg[(size_t)(kv0 + r) * DK + dd];
            *(float4*)&Vs[r * SPAD + dd] = vv;
        }
        __syncthreads();

        // S = (Q*scale) @ K^T   (4x4 per thread)
        float s[4][4] = {};
        #pragma unroll 16
        for (int d = 0; d < 64; d++) {
            float4 a = *(float4*)&Qst[d * SPAD + ty * 4];
            float4 k = *(float4*)&KPs[d * SPAD + tx * 4];
            s[0][0] += a.x * k.x; s[0][1] += a.x * k.y; s[0][2] += a.x * k.z; s[0][3] += a.x * k.w;
            s[1][0] += a.y * k.x; s[1][1] += a.y * k.y; s[1][2] += a.y * k.z; s[1][3] += a.y * k.w;
            s[2][0] += a.z * k.x; s[2][1] += a.z * k.y; s[2][2] += a.z * k.z; s[2][3] += a.z * k.w;
            s[3][0] += a.w * k.x; s[3][1] += a.w * k.y; s[3][2] += a.w * k.z; s[3][3] += a.w * k.w;
        }

        // Online softmax: row reductions across the 16 tx lanes (xor <= 8 stays in group)
        #pragma unroll
        for (int i = 0; i < 4; i++) {
            float mn = fmaxf(fmaxf(s[i][0], s[i][1]), fmaxf(s[i][2], s[i][3]));
            mn = fmaxf(mn, __shfl_xor_sync(0xffffffffu, mn, 8));
            mn = fmaxf(mn, __shfl_xor_sync(0xffffffffu, mn, 4));
            mn = fmaxf(mn, __shfl_xor_sync(0xffffffffu, mn, 2));
            mn = fmaxf(mn, __shfl_xor_sync(0xffffffffu, mn, 1));
            float mt = fmaxf(m_i[i], mn);
            float alpha = __expf(m_i[i] - mt);
            m_i[i] = mt;
            float rs = 0.f;
            #pragma unroll
            for (int j = 0; j < 4; j++) { s[i][j] = __expf(s[i][j] - mt); rs += s[i][j]; }
            rs += __shfl_xor_sync(0xffffffffu, rs, 8);
            rs += __shfl_xor_sync(0xffffffffu, rs, 4);
            rs += __shfl_xor_sync(0xffffffffu, rs, 2);
            rs += __shfl_xor_sync(0xffffffffu, rs, 1);
            l_i[i] = l_i[i] * alpha + rs;
            #pragma unroll
            for (int j = 0; j < 4; j++) acc[i][j] *= alpha;
        }
        __syncthreads();   // everyone done reading Kst before aliasing as Ps

        #pragma unroll
        for (int i = 0; i < 4; i++)
            *(float4*)&KPs[(ty * 4 + i) * SPAD + tx * 4] =
                make_float4(s[i][0], s[i][1], s[i][2], s[i][3]);
        __syncthreads();

        // O += P @ V
        #pragma unroll 16
        for (int k = 0; k < 64; k++) {
            float4 v = *(float4*)&Vs[k * SPAD + tx * 4];
            float p0 = KPs[(ty * 4 + 0) * SPAD + k];
            float p1 = KPs[(ty * 4 + 1) * SPAD + k];
            float p2 = KPs[(ty * 4 + 2) * SPAD + k];
            float p3 = KPs[(ty * 4 + 3) * SPAD + k];
            acc[0][0] += p0 * v.x; acc[0][1] += p0 * v.y; acc[0][2] += p0 * v.z; acc[0][3] += p0 * v.w;
            acc[1][0] += p1 * v.x; acc[1][1] += p1 * v.y; acc[1][2] += p1 * v.z; acc[1][3] += p1 * v.w;
            acc[2][0] += p2 * v.x; acc[2][1] += p2 * v.y; acc[2][2] += p2 * v.z; acc[2][3] += p2 * v.w;
            acc[3][0] += p3 * v.x; acc[3][1] += p3 * v.y; acc[3][2] += p3 * v.z; acc[3][3] += p3 * v.w;
        }
        __syncthreads();   // before next tile overwrites Ps/Vs
    }

    // Epilogue: normalize and write concat layout
    float* Og = g_O + (size_t)b * SEQ * DMODEL + h * DK;
    #pragma unroll
    for (int i = 0; i < 4; i++) {
        float inv = 1.f / l_i[i];
        int r = q0 + ty * 4 + i;
        #pragma unroll
        for (int j = 0; j < 4; j++)
            Og[(size_t)r * DMODEL + tx * 4 + j] = acc[i][j] * inv;
    }
}

// ---------------------------------------------------------------------------
// Kernel 3: output projection (NT GEMM) + bias + residual
// P[r,n] = sum_k O[r,k] * proj_w[n,k] + bias[n] + q[r,n]
// ---------------------------------------------------------------------------
__global__ __launch_bounds__(256) void proj_gemm_kernel(
    const float* __restrict__ Xres,
    const float* __restrict__ Wp,
    const float* __restrict__ bias)
{
    const int row0 = blockIdx.x * 64;
    const int n0   = blockIdx.y * 64;

    __shared__ float Ast[16][SPAD];   // Ast[k][row]
    __shared__ float Bs[16][SPAD];    // Bs[k][n]

    const int tid = threadIdx.x;
    const int tx = tid & 15, ty = tid >> 4;
    const int ar = tid >> 2, ak = (tid & 3) << 2;

    float acc[4][4] = {};

    for (int k0 = 0; k0 < DMODEL; k0 += 16) {
        float4 av = *(const float4*)&g_O[(size_t)(row0 + ar) * DMODEL + k0 + ak];
        Ast[ak + 0][ar] = av.x; Ast[ak + 1][ar] = av.y;
        Ast[ak + 2][ar] = av.z; Ast[ak + 3][ar] = av.w;
        float4 bv = *(const float4*)&Wp[(size_t)(n0 + ar) * DMODEL + k0 + ak];
        Bs[ak + 0][ar] = bv.x; Bs[ak + 1][ar] = bv.y;
        Bs[ak + 2][ar] = bv.z; Bs[ak + 3][ar] = bv.w;
        __syncthreads();
        #pragma unroll
        for (int kk = 0; kk < 16; kk++) {
            float4 a = *(float4*)&Ast[kk][ty * 4];
            float4 b = *(float4*)&Bs[kk][tx * 4];
            acc[0][0] += a.x * b.x; acc[0][1] += a.x * b.y; acc[0][2] += a.x * b.z; acc[0][3] += a.x * b.w;
            acc[1][0] += a.y * b.x; acc[1][1] += a.y * b.y; acc[1][2] += a.y * b.z; acc[1][3] += a.y * b.w;
            acc[2][0] += a.z * b.x; acc[2][1] += a.z * b.y; acc[2][2] += a.z * b.z; acc[2][3] += a.z * b.w;
            acc[3][0] += a.w * b.x; acc[3][1] += a.w * b.y; acc[3][2] += a.w * b.z; acc[3][3] += a.w * b.w;
        }
        __syncthreads();
    }
    #pragma unroll
    for (int i = 0; i < 4; i++) {
        int r = row0 + ty * 4 + i;
        #pragma unroll
        for (int j = 0; j < 4; j++) {
            int n = n0 + tx * 4 + j;
            g_P[(size_t)r * DMODEL + n] = acc[i][j] + bias[n] + Xres[(size_t)r * DMODEL + n];
        }
    }
}

// ---------------------------------------------------------------------------
// Kernel 4: LayerNorm (torch std: ddof=1; divide by sigma + eps), one block/row
// ---------------------------------------------------------------------------
__device__ __forceinline__ float blk_sum256(float v, float* red)
{
    #pragma unroll
    for (int o = 16; o; o >>= 1) v += __shfl_xor_sync(0xffffffffu, v, o);
    __syncthreads();
    if ((threadIdx.x & 31) == 0) red[threadIdx.x >> 5] = v;
    __syncthreads();
    if (threadIdx.x < 32) {
        float t = (threadIdx.x < 8) ? red[threadIdx.x] : 0.f;
        #pragma unroll
        for (int o = 4; o; o >>= 1) t += __shfl_xor_sync(0xffffffffu, t, o);
        if (threadIdx.x == 0) red[0] = t;
    }
    __syncthreads();
    return red[0];
}

__global__ __launch_bounds__(256) void ln_kernel(
    const float* __restrict__ a,
    const float* __restrict__ bb,
    float* __restrict__ out)
{
    __shared__ float z[DMODEL];
    __shared__ float red[8];
    const int row = blockIdx.x;
    const int tid = threadIdx.x;
    const float* src = g_P + (size_t)row * DMODEL;

    float ls = 0.f;
    for (int i = tid; i < DMODEL; i += 256) { float v = src[i]; z[i] = v; ls += v; }
    float mu = blk_sum256(ls, red) * (1.0f / DMODEL);

    float ls2 = 0.f;
    for (int i = tid; i < DMODEL; i += 256) { float d = z[i] - mu; ls2 += d * d; }
    float var = blk_sum256(ls2, red) * (1.0f / (DMODEL - 1));   // ddof=1
    float inv = 1.f / (sqrtf(var) + LN_EPS);

    float* dst = out + (size_t)row * DMODEL;
    for (int i = tid; i < DMODEL; i += 256)
        dst[i] = (z[i] - mu) * inv * a[i] + bb[i];
}

// ---------------------------------------------------------------------------
extern "C" void kernel_launch(void* const* d_in, const int* in_sizes, int n_in,
                              void* d_out, int out_size)
{
    const float* q      = (const float*)d_in[0];
    const float* w_qs   = (const float*)d_in[1];
    const float* w_ks   = (const float*)d_in[2];
    const float* w_vs   = (const float*)d_in[3];
    const float* proj_w = (const float*)d_in[4];
    const float* proj_b = (const float*)d_in[5];
    const float* ln_a   = (const float*)d_in[6];
    const float* ln_b   = (const float*)d_in[7];
    float* out = (float*)d_out;

    const int attn_smem = 3 * 64 * SPAD * (int)sizeof(float);   // 52224 B
    cudaFuncSetAttribute(attn_kernel, cudaFuncAttributeMaxDynamicSharedMemorySize, attn_smem);

    qkv_gemm_kernel<<<dim3(BL / 64, NHEAD, 3), 256>>>(q, w_qs, w_ks, w_vs);
    attn_kernel<<<dim3(SEQ / 64, NHEAD * BATCH), 256, attn_smem>>>();
    proj_gemm_kernel<<<dim3(BL / 64, DMODEL / 64), 256>>>(q, proj_w, proj_b);
    ln_kernel<<<BL, 256>>>(ln_a, ln_b, out);
}

// round 3
// speedup vs baseline: 1.2967x; 1.2967x over previous
#include <cuda_runtime.h>
#include <cuda_bf16.h>
#include <math.h>
#include <stdint.h>

#define BATCH  4
#define SEQ    2048
#define DMODEL 1024
#define NHEAD  16
#define DK     64
#define BL     (BATCH * SEQ)          // 8192
#define SCALE  (1.0f / 32.0f)         // 1/sqrt(DMODEL)
#define LN_EPS 1e-3f
#define SPAD   68

// Scratch (allocation-free rule: __device__ globals)
__device__ float g_Q[NHEAD * BL * DK];     // [h][b][l][dk]
__device__ float g_K[NHEAD * BL * DK];
__device__ float g_V[NHEAD * BL * DK];
__device__ float g_O[BL * DMODEL];         // [b][l][h*64+dv] concat layout
__device__ float g_P[BL * DMODEL];         // proj + bias + residual

// ===========================================================================
// Warp-MMA helpers (baseline PTX — no 'a'-suffix features)
// ===========================================================================
__device__ __forceinline__ uint32_t smem_u32(const void* p) {
    uint32_t a;
    asm("{ .reg .u64 t; cvta.to.shared.u64 t, %1; cvt.u32.u64 %0, t; }" : "=r"(a) : "l"(p));
    return a;
}
__device__ __forceinline__ void ldm4(uint32_t* r, uint32_t addr) {
    asm volatile("ldmatrix.sync.aligned.m8n8.x4.shared.b16 {%0,%1,%2,%3}, [%4];"
        : "=r"(r[0]), "=r"(r[1]), "=r"(r[2]), "=r"(r[3]) : "r"(addr));
}
__device__ __forceinline__ void mma16816(float* c, const uint32_t* a, const uint32_t* b) {
    asm volatile(
        "mma.sync.aligned.m16n8k16.row.col.f32.bf16.bf16.f32 "
        "{%0,%1,%2,%3}, {%4,%5,%6,%7}, {%8,%9}, {%0,%1,%2,%3};"
        : "+f"(c[0]), "+f"(c[1]), "+f"(c[2]), "+f"(c[3])
        : "r"(a[0]), "r"(a[1]), "r"(a[2]), "r"(a[3]), "r"(b[0]), "r"(b[1]));
}

// SW128-style swizzle (16B granules): off ^ ((off>>3)&0x70)
#define SWZ(off) ((off) ^ (((off) >> 3) & 0x70))

__device__ __forceinline__ void bsplit(float x, __nv_bfloat16& h, __nv_bfloat16& l) {
    h = __float2bfloat16(x);
    l = __float2bfloat16(x - __bfloat162float(h));
}
__device__ __forceinline__ uint32_t pack2(__nv_bfloat16 a, __nv_bfloat16 b) {
    uint16_t ua = *(uint16_t*)&a, ub = *(uint16_t*)&b;
    return (uint32_t)ua | ((uint32_t)ub << 16);
}

// ===========================================================================
// bf16x3 MMA GEMM:  C[8192,1024] = A[8192,1024] @ B^T  (B stored [n][k])
// Tile 128x128, K-chunk 64, 8 warps of 64x32, m16n8k16 HMMA.
// mode 0: QKV (blockIdx.z picks w; B[n][k]=w[n>>6][k][n&63]; scatter out)
// mode 1: proj (A=g_O, B=proj_w; fused bias+residual -> g_P)
// ===========================================================================
#define SM_AHI 0
#define SM_ALO 16384
#define SM_BHI 32768
#define SM_BLO 49152
#define SM_TOT 65536

__global__ __launch_bounds__(256, 2) void gemm_mma(
    const float* __restrict__ A,
    const float* __restrict__ W0,
    const float* __restrict__ W1,
    const float* __restrict__ W2,
    const float* __restrict__ bias,
    const float* __restrict__ resid,
    int mode)
{
    extern __shared__ char sm[];
    const uint32_t smb = smem_u32(sm);
    const int tid  = threadIdx.x;
    const int lane = tid & 31, wid = tid >> 5;
    const int wm = wid >> 2, wn = wid & 3;       // warp tile (wm*64, wn*32)
    const int row0 = blockIdx.x * 128;
    const int n0   = blockIdx.y * 128;

    const float* Asrc = (mode == 0) ? A : g_O;
    const float* Wsrc;
    float* Outp;
    if (mode == 0) {
        if (blockIdx.z == 0)      { Wsrc = W0; Outp = g_Q; }
        else if (blockIdx.z == 1) { Wsrc = W1; Outp = g_K; }
        else                      { Wsrc = W2; Outp = g_V; }
    } else { Wsrc = W0; Outp = g_P; }

    // ldmatrix per-thread geometry
    const int grp = lane >> 3, rr = lane & 7;
    const uint32_t swx = (uint32_t)(rr << 4);            // swizzle XOR (constant!)
    const int arowb = wm * 64 + (grp & 1) * 8 + rr;      // + mt*16
    const int akb   = (grp >> 1) * 16;                   // + ks*32 (bytes)
    const int bnb   = wn * 32 + ((grp >> 1) & 1) * 8 + rr; // + pair*16
    const int bkb   = (grp & 1) * 16;                    // + ks*32 (bytes)

    float acc[4][4][4];
    #pragma unroll
    for (int i = 0; i < 4; i++)
        #pragma unroll
        for (int j = 0; j < 4; j++)
            #pragma unroll
            for (int t = 0; t < 4; t++) acc[i][j][t] = 0.f;

    for (int kt = 0; kt < 16; kt++) {
        const int k0 = kt * 64;

        // ---- A tile [128 x 64] fp32 -> bf16 hi/lo (swizzled) ----
        #pragma unroll 2
        for (int i = 0; i < 8; i++) {
            int e = i * 256 + tid;
            int r = e >> 4, cq = (e & 15) << 2;
            float4 v = *(const float4*)&Asrc[(size_t)(row0 + r) * 1024 + k0 + cq];
            __nv_bfloat16 h0, h1, h2, h3, l0, l1, l2, l3;
            bsplit(v.x, h0, l0); bsplit(v.y, h1, l1);
            bsplit(v.z, h2, l2); bsplit(v.w, h3, l3);
            uint32_t sw = SWZ((uint32_t)(r * 128 + cq * 2));
            *(uint2*)(sm + SM_AHI + sw) = make_uint2(pack2(h0, h1), pack2(h2, h3));
            *(uint2*)(sm + SM_ALO + sw) = make_uint2(pack2(l0, l1), pack2(l2, l3));
        }

        // ---- B tile [128 n x 64 k] ----
        if (mode == 1) {
            #pragma unroll 2
            for (int i = 0; i < 8; i++) {
                int e = i * 256 + tid;
                int r = e >> 4, cq = (e & 15) << 2;
                float4 v = *(const float4*)&Wsrc[(size_t)(n0 + r) * 1024 + k0 + cq];
                __nv_bfloat16 h0, h1, h2, h3, l0, l1, l2, l3;
                bsplit(v.x, h0, l0); bsplit(v.y, h1, l1);
                bsplit(v.z, h2, l2); bsplit(v.w, h3, l3);
                uint32_t sw = SWZ((uint32_t)(r * 128 + cq * 2));
                *(uint2*)(sm + SM_BHI + sw) = make_uint2(pack2(h0, h1), pack2(h2, h3));
                *(uint2*)(sm + SM_BLO + sw) = make_uint2(pack2(l0, l1), pack2(l2, l3));
            }
        } else {
            // w layout [h][k][dk]; B[n][k] = w[n>>6][k][n&63]
            const int h0b = n0 >> 6;
            #pragma unroll 2
            for (int i = 0; i < 8; i++) {
                int e = i * 256 + tid;            // float4 group index, 0..2047
                int hh = e >> 10;
                int rem = e & 1023;
                int kk = rem >> 4;
                int dq = (rem & 15) << 2;
                float4 v = *(const float4*)&Wsrc[(size_t)(h0b + hh) * 65536 + (size_t)(k0 + kk) * 64 + dq];
                float vv[4] = {v.x, v.y, v.z, v.w};
                #pragma unroll
                for (int j = 0; j < 4; j++) {
                    __nv_bfloat16 h, l;
                    bsplit(vv[j], h, l);
                    uint32_t sw = SWZ((uint32_t)((hh * 64 + dq + j) * 128 + kk * 2));
                    *(__nv_bfloat16*)(sm + SM_BHI + sw) = h;
                    *(__nv_bfloat16*)(sm + SM_BLO + sw) = l;
                }
            }
        }
        __syncthreads();

        // ---- 4 k-steps of 16 ----
        #pragma unroll
        for (int ks = 0; ks < 4; ks++) {
            uint32_t bh[4][2], bl[4][2];
            #pragma unroll
            for (int pr = 0; pr < 2; pr++) {
                int brow = bnb + pr * 16;
                uint32_t boff = (uint32_t)(brow * 128) + (((uint32_t)(ks * 32 + bkb)) ^ swx);
                uint32_t r4[4];
                ldm4(r4, smb + SM_BHI + boff);
                bh[pr*2][0] = r4[0]; bh[pr*2][1] = r4[1];
                bh[pr*2+1][0] = r4[2]; bh[pr*2+1][1] = r4[3];
                ldm4(r4, smb + SM_BLO + boff);
                bl[pr*2][0] = r4[0]; bl[pr*2][1] = r4[1];
                bl[pr*2+1][0] = r4[2]; bl[pr*2+1][1] = r4[3];
            }
            #pragma unroll
            for (int mt = 0; mt < 4; mt++) {
                int arow = arowb + mt * 16;
                uint32_t aoff = (uint32_t)(arow * 128) + (((uint32_t)(ks * 32 + akb)) ^ swx);
                uint32_t ah[4], al[4];
                ldm4(ah, smb + SM_AHI + aoff);
                ldm4(al, smb + SM_ALO + aoff);
                #pragma unroll
                for (int nt = 0; nt < 4; nt++) {
                    mma16816(acc[mt][nt], ah, bh[nt]);
                    mma16816(acc[mt][nt], ah, bl[nt]);
                    mma16816(acc[mt][nt], al, bh[nt]);
                }
            }
        }
        __syncthreads();
    }

    // ---- epilogue: registers -> gmem ----
    const int l4 = lane >> 2, lm = lane & 3;
    #pragma unroll
    for (int mt = 0; mt < 4; mt++) {
        #pragma unroll
        for (int nt = 0; nt < 4; nt++) {
            int m = row0 + wm * 64 + mt * 16 + l4;
            int n = n0 + wn * 32 + nt * 8 + lm * 2;
            if (mode == 0) {
                int hh = n >> 6, dk = n & 63;
                int b0_ = m >> 11, l0_ = m & 2047;
                float* p0 = &Outp[(((size_t)(hh * 4 + b0_)) * 2048 + l0_) * 64 + dk];
                *(float2*)p0 = make_float2(acc[mt][nt][0], acc[mt][nt][1]);
                int m2 = m + 8;
                int b1_ = m2 >> 11, l1_ = m2 & 2047;
                float* p1 = &Outp[(((size_t)(hh * 4 + b1_)) * 2048 + l1_) * 64 + dk];
                *(float2*)p1 = make_float2(acc[mt][nt][2], acc[mt][nt][3]);
            } else {
                float2 bv = *(const float2*)&bias[n];
                float2 r0v = *(const float2*)&resid[(size_t)m * 1024 + n];
                float2 r1v = *(const float2*)&resid[(size_t)(m + 8) * 1024 + n];
                *(float2*)&Outp[(size_t)m * 1024 + n] =
                    make_float2(acc[mt][nt][0] + bv.x + r0v.x, acc[mt][nt][1] + bv.y + r0v.y);
                *(float2*)&Outp[(size_t)(m + 8) * 1024 + n] =
                    make_float2(acc[mt][nt][2] + bv.x + r1v.x, acc[mt][nt][3] + bv.y + r1v.y);
            }
        }
    }
}

// ---------------------------------------------------------------------------
// Flash attention (SIMT fp32).  Per (head,batch): [2048,64]
// ---------------------------------------------------------------------------
__global__ __launch_bounds__(256) void attn_kernel()
{
    extern __shared__ float smf[];
    float* Qst = smf;
    float* KPs = smf + 64 * SPAD;
    float* Vs  = smf + 2 * 64 * SPAD;

    const int tid = threadIdx.x;
    const int tx = tid & 15, ty = tid >> 4;
    const int h = blockIdx.y >> 2, b = blockIdx.y & 3;
    const size_t base = (size_t)(h * BATCH + b) * SEQ * DK;
    const float* Qg = g_Q + base;
    const float* Kg = g_K + base;
    const float* Vg = g_V + base;
    const int q0 = blockIdx.x * 64;

    for (int e = tid; e < 1024; e += 256) {
        int r = e >> 4, dd = (e & 15) << 2;
        float4 v = *(const float4*)&Qg[(size_t)(q0 + r) * DK + dd];
        Qst[(dd + 0) * SPAD + r] = v.x * SCALE;
        Qst[(dd + 1) * SPAD + r] = v.y * SCALE;
        Qst[(dd + 2) * SPAD + r] = v.z * SCALE;
        Qst[(dd + 3) * SPAD + r] = v.w * SCALE;
    }

    float m_i[4], l_i[4], acc[4][4];
    #pragma unroll
    for (int i = 0; i < 4; i++) {
        m_i[i] = -1e30f; l_i[i] = 0.f;
        #pragma unroll
        for (int j = 0; j < 4; j++) acc[i][j] = 0.f;
    }
    __syncthreads();

    for (int kv0 = 0; kv0 < SEQ; kv0 += 64) {
        for (int e = tid; e < 1024; e += 256) {
            int r = e >> 4, dd = (e & 15) << 2;
            float4 kv = *(const float4*)&Kg[(size_t)(kv0 + r) * DK + dd];
            KPs[(dd + 0) * SPAD + r] = kv.x;
            KPs[(dd + 1) * SPAD + r] = kv.y;
            KPs[(dd + 2) * SPAD + r] = kv.z;
            KPs[(dd + 3) * SPAD + r] = kv.w;
            float4 vv = *(const float4*)&Vg[(size_t)(kv0 + r) * DK + dd];
            *(float4*)&Vs[r * SPAD + dd] = vv;
        }
        __syncthreads();

        float s[4][4] = {};
        #pragma unroll 16
        for (int d = 0; d < 64; d++) {
            float4 a = *(float4*)&Qst[d * SPAD + ty * 4];
            float4 k = *(float4*)&KPs[d * SPAD + tx * 4];
            s[0][0] += a.x * k.x; s[0][1] += a.x * k.y; s[0][2] += a.x * k.z; s[0][3] += a.x * k.w;
            s[1][0] += a.y * k.x; s[1][1] += a.y * k.y; s[1][2] += a.y * k.z; s[1][3] += a.y * k.w;
            s[2][0] += a.z * k.x; s[2][1] += a.z * k.y; s[2][2] += a.z * k.z; s[2][3] += a.z * k.w;
            s[3][0] += a.w * k.x; s[3][1] += a.w * k.y; s[3][2] += a.w * k.z; s[3][3] += a.w * k.w;
        }

        #pragma unroll
        for (int i = 0; i < 4; i++) {
            float mn = fmaxf(fmaxf(s[i][0], s[i][1]), fmaxf(s[i][2], s[i][3]));
            mn = fmaxf(mn, __shfl_xor_sync(0xffffffffu, mn, 8));
            mn = fmaxf(mn, __shfl_xor_sync(0xffffffffu, mn, 4));
            mn = fmaxf(mn, __shfl_xor_sync(0xffffffffu, mn, 2));
            mn = fmaxf(mn, __shfl_xor_sync(0xffffffffu, mn, 1));
            float mt = fmaxf(m_i[i], mn);
            float alpha = __expf(m_i[i] - mt);
            m_i[i] = mt;
            float rs = 0.f;
            #pragma unroll
            for (int j = 0; j < 4; j++) { s[i][j] = __expf(s[i][j] - mt); rs += s[i][j]; }
            rs += __shfl_xor_sync(0xffffffffu, rs, 8);
            rs += __shfl_xor_sync(0xffffffffu, rs, 4);
            rs += __shfl_xor_sync(0xffffffffu, rs, 2);
            rs += __shfl_xor_sync(0xffffffffu, rs, 1);
            l_i[i] = l_i[i] * alpha + rs;
            #pragma unroll
            for (int j = 0; j < 4; j++) acc[i][j] *= alpha;
        }
        __syncthreads();

        #pragma unroll
        for (int i = 0; i < 4; i++)
            *(float4*)&KPs[(ty * 4 + i) * SPAD + tx * 4] =
                make_float4(s[i][0], s[i][1], s[i][2], s[i][3]);
        __syncthreads();

        #pragma unroll 16
        for (int k = 0; k < 64; k++) {
            float4 v = *(float4*)&Vs[k * SPAD + tx * 4];
            float p0 = KPs[(ty * 4 + 0) * SPAD + k];
            float p1 = KPs[(ty * 4 + 1) * SPAD + k];
            float p2 = KPs[(ty * 4 + 2) * SPAD + k];
            float p3 = KPs[(ty * 4 + 3) * SPAD + k];
            acc[0][0] += p0 * v.x; acc[0][1] += p0 * v.y; acc[0][2] += p0 * v.z; acc[0][3] += p0 * v.w;
            acc[1][0] += p1 * v.x; acc[1][1] += p1 * v.y; acc[1][2] += p1 * v.z; acc[1][3] += p1 * v.w;
            acc[2][0] += p2 * v.x; acc[2][1] += p2 * v.y; acc[2][2] += p2 * v.z; acc[2][3] += p2 * v.w;
            acc[3][0] += p3 * v.x; acc[3][1] += p3 * v.y; acc[3][2] += p3 * v.z; acc[3][3] += p3 * v.w;
        }
        __syncthreads();
    }

    float* Og = g_O + (size_t)b * SEQ * DMODEL + h * DK;
    #pragma unroll
    for (int i = 0; i < 4; i++) {
        float inv = 1.f / l_i[i];
        int r = q0 + ty * 4 + i;
        #pragma unroll
        for (int j = 0; j < 4; j++)
            Og[(size_t)r * DMODEL + tx * 4 + j] = acc[i][j] * inv;
    }
}

// ---------------------------------------------------------------------------
// LayerNorm (ddof=1; divide by sigma + eps), one block/row
// ---------------------------------------------------------------------------
__device__ __forceinline__ float blk_sum256(float v, float* red)
{
    #pragma unroll
    for (int o = 16; o; o >>= 1) v += __shfl_xor_sync(0xffffffffu, v, o);
    __syncthreads();
    if ((threadIdx.x & 31) == 0) red[threadIdx.x >> 5] = v;
    __syncthreads();
    if (threadIdx.x < 32) {
        float t = (threadIdx.x < 8) ? red[threadIdx.x] : 0.f;
        #pragma unroll
        for (int o = 4; o; o >>= 1) t += __shfl_xor_sync(0xffffffffu, t, o);
        if (threadIdx.x == 0) red[0] = t;
    }
    __syncthreads();
    return red[0];
}

__global__ __launch_bounds__(256) void ln_kernel(
    const float* __restrict__ a,
    const float* __restrict__ bb,
    float* __restrict__ out)
{
    __shared__ float z[DMODEL];
    __shared__ float red[8];
    const int row = blockIdx.x;
    const int tid = threadIdx.x;
    const float* src = g_P + (size_t)row * DMODEL;

    float ls = 0.f;
    for (int i = tid; i < DMODEL; i += 256) { float v = src[i]; z[i] = v; ls += v; }
    float mu = blk_sum256(ls, red) * (1.0f / DMODEL);

    float ls2 = 0.f;
    for (int i = tid; i < DMODEL; i += 256) { float d = z[i] - mu; ls2 += d * d; }
    float var = blk_sum256(ls2, red) * (1.0f / (DMODEL - 1));
    float inv = 1.f / (sqrtf(var) + LN_EPS);

    float* dst = out + (size_t)row * DMODEL;
    for (int i = tid; i < DMODEL; i += 256)
        dst[i] = (z[i] - mu) * inv * a[i] + bb[i];
}

// ---------------------------------------------------------------------------
extern "C" void kernel_launch(void* const* d_in, const int* in_sizes, int n_in,
                              void* d_out, int out_size)
{
    const float* q      = (const float*)d_in[0];
    const float* w_qs   = (const float*)d_in[1];
    const float* w_ks   = (const float*)d_in[2];
    const float* w_vs   = (const float*)d_in[3];
    const float* proj_w = (const float*)d_in[4];
    const float* proj_b = (const float*)d_in[5];
    const float* ln_a   = (const float*)d_in[6];
    const float* ln_b   = (const float*)d_in[7];
    float* out = (float*)d_out;

    const int attn_smem = 3 * 64 * SPAD * (int)sizeof(float);   // 52224 B
    cudaFuncSetAttribute(attn_kernel, cudaFuncAttributeMaxDynamicSharedMemorySize, attn_smem);
    cudaFuncSetAttribute(gemm_mma, cudaFuncAttributeMaxDynamicSharedMemorySize, SM_TOT);

    // QKV: 3 GEMMs [8192,1024]@[1024,1024] (heads folded into N)
    gemm_mma<<<dim3(64, 8, 3), 256, SM_TOT>>>(q, w_qs, w_ks, w_vs, nullptr, nullptr, 0);
    // Flash attention (fp32 SIMT)
    attn_kernel<<<dim3(SEQ / 64, NHEAD * BATCH), 256, attn_smem>>>();
    // Output projection + bias + residual
    gemm_mma<<<dim3(64, 8, 1), 256, SM_TOT>>>(nullptr, proj_w, nullptr, nullptr, proj_b, q, 1);
    // LayerNorm
    ln_kernel<<<BL, 256>>>(ln_a, ln_b, out);
}

// round 5
// speedup vs baseline: 2.3147x; 1.7851x over previous
#include <cuda_runtime.h>
#include <cuda_bf16.h>
#include <math.h>
#include <stdint.h>

#define BATCH  4
#define SEQ    2048
#define DMODEL 1024
#define NHEAD  16
#define DK     64
#define BL     (BATCH * SEQ)          // 8192
#define SCALE  (1.0f / 32.0f)         // 1/sqrt(DMODEL)
#define LN_EPS 1e-3f

// Scratch (allocation-free rule: __device__ globals)
__device__ __nv_bfloat16 g_Qh[NHEAD * BL * DK];  // [h*4+b][l][dk], scaled
__device__ __nv_bfloat16 g_Ql[NHEAD * BL * DK];
__device__ __nv_bfloat16 g_Kh[NHEAD * BL * DK];
__device__ __nv_bfloat16 g_Kl[NHEAD * BL * DK];
__device__ __nv_bfloat16 g_Vh[NHEAD * BL * DK];
__device__ __nv_bfloat16 g_Vl[NHEAD * BL * DK];
__device__ float g_O[BL * DMODEL];               // attention out, concat layout
__device__ float g_P[BL * DMODEL];               // proj + bias + residual

// ===========================================================================
// PTX helpers (baseline PTX — no 'a'-suffix features)
// ===========================================================================
__device__ __forceinline__ uint32_t smem_u32(const void* p) {
    uint32_t a;
    asm("{ .reg .u64 t; cvta.to.shared.u64 t, %1; cvt.u32.u64 %0, t; }" : "=r"(a) : "l"(p));
    return a;
}
__device__ __forceinline__ void ldm4(uint32_t* r, uint32_t addr) {
    asm volatile("ldmatrix.sync.aligned.m8n8.x4.shared.b16 {%0,%1,%2,%3}, [%4];"
        : "=r"(r[0]), "=r"(r[1]), "=r"(r[2]), "=r"(r[3]) : "r"(addr));
}
__device__ __forceinline__ void ldm4t(uint32_t* r, uint32_t addr) {
    asm volatile("ldmatrix.sync.aligned.m8n8.x4.trans.shared.b16 {%0,%1,%2,%3}, [%4];"
        : "=r"(r[0]), "=r"(r[1]), "=r"(r[2]), "=r"(r[3]) : "r"(addr));
}
__device__ __forceinline__ void mma16816(float* c, const uint32_t* a, const uint32_t* b) {
    asm volatile(
        "mma.sync.aligned.m16n8k16.row.col.f32.bf16.bf16.f32 "
        "{%0,%1,%2,%3}, {%4,%5,%6,%7}, {%8,%9}, {%0,%1,%2,%3};"
        : "+f"(c[0]), "+f"(c[1]), "+f"(c[2]), "+f"(c[3])
        : "r"(a[0]), "r"(a[1]), "r"(a[2]), "r"(a[3]), "r"(b[0]), "r"(b[1]));
}
__device__ __forceinline__ void cpa16(uint32_t dst, const void* src) {
    asm volatile("cp.async.cg.shared.global [%0], [%1], 16;" :: "r"(dst), "l"(src));
}
__device__ __forceinline__ void cpa_commit() { asm volatile("cp.async.commit_group;"); }
template<int N> __device__ __forceinline__ void cpa_wait() {
    asm volatile("cp.async.wait_group %0;" :: "n"(N));
}

// SW128-style swizzle (16B granules)
#define SWZ(off) ((off) ^ (((off) >> 3) & 0x70))

__device__ __forceinline__ void bsplit(float x, __nv_bfloat16& h, __nv_bfloat16& l) {
    h = __float2bfloat16(x);
    l = __float2bfloat16(x - __bfloat162float(h));
}
__device__ __forceinline__ uint32_t pack2(__nv_bfloat16 a, __nv_bfloat16 b) {
    uint16_t ua = *(uint16_t*)&a, ub = *(uint16_t*)&b;
    return (uint32_t)ua | ((uint32_t)ub << 16);
}

// ===========================================================================
// bf16x3 MMA GEMM (QKV: epilogue splits to bf16 hi/lo; proj: bias+residual)
// ===========================================================================
#define SM_AHI 0
#define SM_ALO 16384
#define SM_BHI 32768
#define SM_BLO 49152
#define SM_TOT 65536

__global__ __launch_bounds__(256, 2) void gemm_mma(
    const float* __restrict__ A,
    const float* __restrict__ W0,
    const float* __restrict__ W1,
    const float* __restrict__ W2,
    const float* __restrict__ bias,
    const float* __restrict__ resid,
    int mode)
{
    extern __shared__ char sm[];
    const uint32_t smb = smem_u32(sm);
    const int tid  = threadIdx.x;
    const int lane = tid & 31, wid = tid >> 5;
    const int wm = wid >> 2, wn = wid & 3;
    const int row0 = blockIdx.x * 128;
    const int n0   = blockIdx.y * 128;

    const float* Asrc = (mode == 0) ? A : g_O;
    const float* Wsrc;
    __nv_bfloat16 *SpH = nullptr, *SpL = nullptr;
    float sc = 1.0f;
    if (mode == 0) {
        if (blockIdx.z == 0)      { Wsrc = W0; SpH = g_Qh; SpL = g_Ql; sc = SCALE; }
        else if (blockIdx.z == 1) { Wsrc = W1; SpH = g_Kh; SpL = g_Kl; }
        else                      { Wsrc = W2; SpH = g_Vh; SpL = g_Vl; }
    } else { Wsrc = W0; }

    const int grp = lane >> 3, rr = lane & 7;
    const uint32_t swx = (uint32_t)(rr << 4);
    const int arowb = wm * 64 + (grp & 1) * 8 + rr;
    const int akb   = (grp >> 1) * 16;
    const int bnb   = wn * 32 + ((grp >> 1) & 1) * 8 + rr;
    const int bkb   = (grp & 1) * 16;

    float acc[4][4][4];
    #pragma unroll
    for (int i = 0; i < 4; i++)
        #pragma unroll
        for (int j = 0; j < 4; j++)
            #pragma unroll
            for (int t = 0; t < 4; t++) acc[i][j][t] = 0.f;

    for (int kt = 0; kt < 16; kt++) {
        const int k0 = kt * 64;

        #pragma unroll 2
        for (int i = 0; i < 8; i++) {
            int e = i * 256 + tid;
            int r = e >> 4, cq = (e & 15) << 2;
            float4 v = *(const float4*)&Asrc[(size_t)(row0 + r) * 1024 + k0 + cq];
            __nv_bfloat16 h0, h1, h2, h3, l0, l1, l2, l3;
            bsplit(v.x, h0, l0); bsplit(v.y, h1, l1);
            bsplit(v.z, h2, l2); bsplit(v.w, h3, l3);
            uint32_t sw = SWZ((uint32_t)(r * 128 + cq * 2));
            *(uint2*)(sm + SM_AHI + sw) = make_uint2(pack2(h0, h1), pack2(h2, h3));
            *(uint2*)(sm + SM_ALO + sw) = make_uint2(pack2(l0, l1), pack2(l2, l3));
        }

        if (mode == 1) {
            #pragma unroll 2
            for (int i = 0; i < 8; i++) {
                int e = i * 256 + tid;
                int r = e >> 4, cq = (e & 15) << 2;
                float4 v = *(const float4*)&Wsrc[(size_t)(n0 + r) * 1024 + k0 + cq];
                __nv_bfloat16 h0, h1, h2, h3, l0, l1, l2, l3;
                bsplit(v.x, h0, l0); bsplit(v.y, h1, l1);
                bsplit(v.z, h2, l2); bsplit(v.w, h3, l3);
                uint32_t sw = SWZ((uint32_t)(r * 128 + cq * 2));
                *(uint2*)(sm + SM_BHI + sw) = make_uint2(pack2(h0, h1), pack2(h2, h3));
                *(uint2*)(sm + SM_BLO + sw) = make_uint2(pack2(l0, l1), pack2(l2, l3));
            }
        } else {
            const int h0b = n0 >> 6;
            #pragma unroll 2
            for (int i = 0; i < 8; i++) {
                int e = i * 256 + tid;
                int hh = e >> 10;
                int rem = e & 1023;
                int kk = rem >> 4;
                int dq = (rem & 15) << 2;
                float4 v = *(const float4*)&Wsrc[(size_t)(h0b + hh) * 65536 + (size_t)(k0 + kk) * 64 + dq];
                float vv[4] = {v.x, v.y, v.z, v.w};
                #pragma unroll
                for (int j = 0; j < 4; j++) {
                    __nv_bfloat16 h, l;
                    bsplit(vv[j], h, l);
                    uint32_t sw = SWZ((uint32_t)((hh * 64 + dq + j) * 128 + kk * 2));
                    *(__nv_bfloat16*)(sm + SM_BHI + sw) = h;
                    *(__nv_bfloat16*)(sm + SM_BLO + sw) = l;
                }
            }
        }
        __syncthreads();

        #pragma unroll
        for (int ks = 0; ks < 4; ks++) {
            uint32_t bh[4][2], bl[4][2];
            #pragma unroll
            for (int pr = 0; pr < 2; pr++) {
                int brow = bnb + pr * 16;
                uint32_t boff = (uint32_t)(brow * 128) + (((uint32_t)(ks * 32 + bkb)) ^ swx);
                uint32_t r4[4];
                ldm4(r4, smb + SM_BHI + boff);
                bh[pr*2][0] = r4[0]; bh[pr*2][1] = r4[1];
                bh[pr*2+1][0] = r4[2]; bh[pr*2+1][1] = r4[3];
                ldm4(r4, smb + SM_BLO + boff);
                bl[pr*2][0] = r4[0]; bl[pr*2][1] = r4[1];
                bl[pr*2+1][0] = r4[2]; bl[pr*2+1][1] = r4[3];
            }
            #pragma unroll
            for (int mt = 0; mt < 4; mt++) {
                int arow = arowb + mt * 16;
                uint32_t aoff = (uint32_t)(arow * 128) + (((uint32_t)(ks * 32 + akb)) ^ swx);
                uint32_t ah[4], al[4];
                ldm4(ah, smb + SM_AHI + aoff);
                ldm4(al, smb + SM_ALO + aoff);
                #pragma unroll
                for (int nt = 0; nt < 4; nt++) {
                    mma16816(acc[mt][nt], ah, bh[nt]);
                    mma16816(acc[mt][nt], ah, bl[nt]);
                    mma16816(acc[mt][nt], al, bh[nt]);
                }
            }
        }
        __syncthreads();
    }

    // ---- epilogue ----
    const int l4 = lane >> 2, lm = lane & 3;
    #pragma unroll
    for (int mt = 0; mt < 4; mt++) {
        #pragma unroll
        for (int nt = 0; nt < 4; nt++) {
            int m = row0 + wm * 64 + mt * 16 + l4;
            int n = n0 + wn * 32 + nt * 8 + lm * 2;
            if (mode == 0) {
                int hh = n >> 6, dk = n & 63;
                float v0 = acc[mt][nt][0] * sc, v1 = acc[mt][nt][1] * sc;
                float v2 = acc[mt][nt][2] * sc, v3 = acc[mt][nt][3] * sc;
                __nv_bfloat16 h0, h1, h2, h3, L0, L1, L2, L3;
                bsplit(v0, h0, L0); bsplit(v1, h1, L1);
                bsplit(v2, h2, L2); bsplit(v3, h3, L3);
                int b0_ = m >> 11, l0_ = m & 2047;
                size_t i0 = (((size_t)(hh * 4 + b0_)) * 2048 + l0_) * 64 + dk;
                *(uint32_t*)&SpH[i0] = pack2(h0, h1);
                *(uint32_t*)&SpL[i0] = pack2(L0, L1);
                int m2 = m + 8;
                int b1_ = m2 >> 11, l1_ = m2 & 2047;
                size_t i1 = (((size_t)(hh * 4 + b1_)) * 2048 + l1_) * 64 + dk;
                *(uint32_t*)&SpH[i1] = pack2(h2, h3);
                *(uint32_t*)&SpL[i1] = pack2(L2, L3);
            } else {
                float2 bv = *(const float2*)&bias[n];
                float2 r0v = *(const float2*)&resid[(size_t)m * 1024 + n];
                float2 r1v = *(const float2*)&resid[(size_t)(m + 8) * 1024 + n];
                *(float2*)&g_P[(size_t)m * 1024 + n] =
                    make_float2(acc[mt][nt][0] + bv.x + r0v.x, acc[mt][nt][1] + bv.y + r0v.y);
                *(float2*)&g_P[(size_t)(m + 8) * 1024 + n] =
                    make_float2(acc[mt][nt][2] + bv.x + r1v.x, acc[mt][nt][3] + bv.y + r1v.y);
            }
        }
    }
}

// ===========================================================================
// Flash attention, HMMA bf16x3.  CTA: 128 q-rows, 8 warps x 16 rows, BK=64.
// cp.async double-buffered K/V tiles (pre-split bf16 hi/lo in gmem).
// ===========================================================================
#define AT_STAGE 32768   // per-stage: KH 0 | KL 8192 | VH 16384 | VL 24576
#define AT_TOT   65536

__global__ __launch_bounds__(256) void attn_mma()
{
    extern __shared__ char sm[];
    const uint32_t smb = smem_u32(sm);
    const int tid = threadIdx.x, lane = tid & 31, wid = tid >> 5;
    const int h = blockIdx.y >> 2, b = blockIdx.y & 3;
    const size_t base = (size_t)(h * BATCH + b) * SEQ * DK;
    const __nv_bfloat16* Qh = g_Qh + base;
    const __nv_bfloat16* Ql = g_Ql + base;
    const __nv_bfloat16* Kh = g_Kh + base;
    const __nv_bfloat16* Kl = g_Kl + base;
    const __nv_bfloat16* Vh = g_Vh + base;
    const __nv_bfloat16* Vl = g_Vl + base;
    const int q0 = blockIdx.x * 128;

    const int grp = lane >> 3, rr = lane & 7;
    const uint32_t swx = (uint32_t)(rr << 4);

    // ---- stage Q (128x64) hi then lo through smem; keep A-frags in regs ----
    uint32_t qha[4][4], qla[4][4];
    const uint32_t qaoff_base = (uint32_t)((wid * 16 + (grp & 1) * 8 + rr) * 128);
    #pragma unroll
    for (int ph = 0; ph < 2; ph++) {
        const __nv_bfloat16* Qs = ph ? Ql : Qh;
        #pragma unroll
        for (int i = 0; i < 4; i++) {
            int g = i * 256 + tid;           // 0..1023 granules (128 rows x 8)
            int r = g >> 3, c = g & 7;
            uint4 v = *(const uint4*)&Qs[(size_t)(q0 + r) * DK + c * 8];
            *(uint4*)(sm + (r * 128 + ((c * 16) ^ ((r & 7) << 4)))) = v;
        }
        __syncthreads();
        #pragma unroll
        for (int ks = 0; ks < 4; ks++) {
            uint32_t aoff = qaoff_base + (((uint32_t)(ks * 32 + (grp >> 1) * 16)) ^ swx);
            if (ph == 0) ldm4(qha[ks], smb + aoff);
            else         ldm4(qla[ks], smb + aoff);
        }
        __syncthreads();
    }

    float o[8][4];
    #pragma unroll
    for (int i = 0; i < 8; i++)
        #pragma unroll
        for (int j = 0; j < 4; j++) o[i][j] = 0.f;
    float m0 = -1e30f, m1 = -1e30f, l0 = 0.f, l1 = 0.f;

    // loader: 512 granules per array, 2 per thread
    const int lg0 = tid, lg1 = tid + 256;
    #define ISSUE_TILE(kv0, stg) do {                                           \
        int rA = lg0 >> 3, cA = lg0 & 7;                                        \
        uint32_t dA = (stg) + (uint32_t)(rA * 128 + ((cA * 16) ^ ((rA & 7) << 4))); \
        size_t sA = (size_t)((kv0) + rA) * DK + cA * 8;                         \
        cpa16(dA,          &Kh[sA]); cpa16(dA + 8192,  &Kl[sA]);                \
        cpa16(dA + 16384,  &Vh[sA]); cpa16(dA + 24576, &Vl[sA]);                \
        int rB = lg1 >> 3, cB = lg1 & 7;                                        \
        uint32_t dB = (stg) + (uint32_t)(rB * 128 + ((cB * 16) ^ ((rB & 7) << 4))); \
        size_t sB = (size_t)((kv0) + rB) * DK + cB * 8;                         \
        cpa16(dB,          &Kh[sB]); cpa16(dB + 8192,  &Kl[sB]);                \
        cpa16(dB + 16384,  &Vh[sB]); cpa16(dB + 24576, &Vl[sB]);                \
    } while (0)

    ISSUE_TILE(0, smb);
    cpa_commit();

    const uint32_t kboff_base = (uint32_t)((((grp >> 1) & 1) * 8 + rr) * 128);
    const int vkey = lane & 15, vdvb = (lane >> 4) * 8;

    for (int t = 0; t < 32; t++) {
        uint32_t stg = smb + (uint32_t)((t & 1) * AT_STAGE);
        if (t < 31) {
            ISSUE_TILE((t + 1) * 64, smb + (uint32_t)(((t + 1) & 1) * AT_STAGE));
            cpa_commit();
            cpa_wait<1>();
        } else {
            cpa_wait<0>();
        }
        __syncthreads();

        // ---- S = Qh*Kh + Qh*Kl + Ql*Kh  (16 q-rows x 64 keys per warp) ----
        float s[8][4];
        #pragma unroll
        for (int i = 0; i < 8; i++)
            #pragma unroll
            for (int j = 0; j < 4; j++) s[i][j] = 0.f;

        #pragma unroll
        for (int ks = 0; ks < 4; ks++) {
            #pragma unroll
            for (int pr = 0; pr < 4; pr++) {
                uint32_t boff = (uint32_t)(pr * 16 * 128) + kboff_base
                              + (((uint32_t)(ks * 32 + (grp & 1) * 16)) ^ swx);
                uint32_t kh4[4], kl4[4];
                ldm4(kh4, stg + boff);
                ldm4(kl4, stg + 8192 + boff);
                mma16816(s[2*pr],   qha[ks], kh4);
                mma16816(s[2*pr+1], qha[ks], kh4 + 2);
                mma16816(s[2*pr],   qha[ks], kl4);
                mma16816(s[2*pr+1], qha[ks], kl4 + 2);
                mma16816(s[2*pr],   qla[ks], kh4);
                mma16816(s[2*pr+1], qla[ks], kh4 + 2);
            }
        }

        // ---- online softmax (rows r=lane>>2 and r+8; quad shuffles) ----
        float a0 = -1e30f, a1 = -1e30f;
        #pragma unroll
        for (int nt = 0; nt < 8; nt++) {
            a0 = fmaxf(a0, fmaxf(s[nt][0], s[nt][1]));
            a1 = fmaxf(a1, fmaxf(s[nt][2], s[nt][3]));
        }
        a0 = fmaxf(a0, __shfl_xor_sync(0xffffffffu, a0, 1));
        a0 = fmaxf(a0, __shfl_xor_sync(0xffffffffu, a0, 2));
        a1 = fmaxf(a1, __shfl_xor_sync(0xffffffffu, a1, 1));
        a1 = fmaxf(a1, __shfl_xor_sync(0xffffffffu, a1, 2));
        float nm0 = fmaxf(m0, a0), nm1 = fmaxf(m1, a1);
        float alpha0 = __expf(m0 - nm0), alpha1 = __expf(m1 - nm1);
        m0 = nm0; m1 = nm1;

        float rs0 = 0.f, rs1 = 0.f;
        #pragma unroll
        for (int nt = 0; nt < 8; nt++) {
            s[nt][0] = __expf(s[nt][0] - nm0); rs0 += s[nt][0];
            s[nt][1] = __expf(s[nt][1] - nm0); rs0 += s[nt][1];
            s[nt][2] = __expf(s[nt][2] - nm1); rs1 += s[nt][2];
            s[nt][3] = __expf(s[nt][3] - nm1); rs1 += s[nt][3];
        }
        rs0 += __shfl_xor_sync(0xffffffffu, rs0, 1);
        rs0 += __shfl_xor_sync(0xffffffffu, rs0, 2);
        rs1 += __shfl_xor_sync(0xffffffffu, rs1, 1);
        rs1 += __shfl_xor_sync(0xffffffffu, rs1, 2);
        l0 = l0 * alpha0 + rs0;
        l1 = l1 * alpha1 + rs1;
        #pragma unroll
        for (int nt = 0; nt < 8; nt++) {
            o[nt][0] *= alpha0; o[nt][1] *= alpha0;
            o[nt][2] *= alpha1; o[nt][3] *= alpha1;
        }

        // ---- pack P hi/lo into A-frag layout (accumulator == A-frag trick) ----
        uint32_t pah[4][4], pal[4][4];
        #pragma unroll
        for (int ss = 0; ss < 4; ss++) {
            __nv_bfloat16 h0, h1, L0, L1;
            bsplit(s[2*ss][0], h0, L0); bsplit(s[2*ss][1], h1, L1);
            pah[ss][0] = pack2(h0, h1); pal[ss][0] = pack2(L0, L1);
            bsplit(s[2*ss][2], h0, L0); bsplit(s[2*ss][3], h1, L1);
            pah[ss][1] = pack2(h0, h1); pal[ss][1] = pack2(L0, L1);
            bsplit(s[2*ss+1][0], h0, L0); bsplit(s[2*ss+1][1], h1, L1);
            pah[ss][2] = pack2(h0, h1); pal[ss][2] = pack2(L0, L1);
            bsplit(s[2*ss+1][2], h0, L0); bsplit(s[2*ss+1][3], h1, L1);
            pah[ss][3] = pack2(h0, h1); pal[ss][3] = pack2(L0, L1);
        }

        // ---- O += Ph*Vh + Ph*Vl + Pl*Vh  (V via ldmatrix.trans) ----
        #pragma unroll
        for (int ss = 0; ss < 4; ss++) {
            #pragma unroll
            for (int dp = 0; dp < 4; dp++) {
                int key = ss * 16 + vkey;
                int dvc = dp * 16 + vdvb;
                uint32_t voff = (uint32_t)(key * 128 + ((dvc * 2) ^ ((key & 7) << 4)));
                uint32_t vh4[4], vl4[4];
                ldm4t(vh4, stg + 16384 + voff);
                ldm4t(vl4, stg + 24576 + voff);
                mma16816(o[2*dp],   pah[ss], vh4);
                mma16816(o[2*dp+1], pah[ss], vh4 + 2);
                mma16816(o[2*dp],   pah[ss], vl4);
                mma16816(o[2*dp+1], pah[ss], vl4 + 2);
                mma16816(o[2*dp],   pal[ss], vh4);
                mma16816(o[2*dp+1], pal[ss], vh4 + 2);
            }
        }
        __syncthreads();
    }

    // ---- epilogue: O /= l, write concat layout [b][l][h*64+dv] ----
    float il0 = 1.f / l0, il1 = 1.f / l1;
    int r0_ = q0 + wid * 16 + (lane >> 2);
    float* Og = g_O + (size_t)b * SEQ * DMODEL + h * 64;
    #pragma unroll
    for (int nt = 0; nt < 8; nt++) {
        int dv = nt * 8 + (lane & 3) * 2;
        *(float2*)&Og[(size_t)r0_ * DMODEL + dv] =
            make_float2(o[nt][0] * il0, o[nt][1] * il0);
        *(float2*)&Og[(size_t)(r0_ + 8) * DMODEL + dv] =
            make_float2(o[nt][2] * il1, o[nt][3] * il1);
    }
}

// ---------------------------------------------------------------------------
// LayerNorm (ddof=1; divide by sigma + eps), one block/row
// ---------------------------------------------------------------------------
__device__ __forceinline__ float blk_sum256(float v, float* red)
{
    #pragma unroll
    for (int o = 16; o; o >>= 1) v += __shfl_xor_sync(0xffffffffu, v, o);
    __syncthreads();
    if ((threadIdx.x & 31) == 0) red[threadIdx.x >> 5] = v;
    __syncthreads();
    if (threadIdx.x < 32) {
        float t = (threadIdx.x < 8) ? red[threadIdx.x] : 0.f;
        #pragma unroll
        for (int o = 4; o; o >>= 1) t += __shfl_xor_sync(0xffffffffu, t, o);
        if (threadIdx.x == 0) red[0] = t;
    }
    __syncthreads();
    return red[0];
}

__global__ __launch_bounds__(256) void ln_kernel(
    const float* __restrict__ a,
    const float* __restrict__ bb,
    float* __restrict__ out)
{
    __shared__ float z[DMODEL];
    __shared__ float red[8];
    const int row = blockIdx.x;
    const int tid = threadIdx.x;
    const float* src = g_P + (size_t)row * DMODEL;

    float ls = 0.f;
    for (int i = tid; i < DMODEL; i += 256) { float v = src[i]; z[i] = v; ls += v; }
    float mu = blk_sum256(ls, red) * (1.0f / DMODEL);

    float ls2 = 0.f;
    for (int i = tid; i < DMODEL; i += 256) { float d = z[i] - mu; ls2 += d * d; }
    float var = blk_sum256(ls2, red) * (1.0f / (DMODEL - 1));
    float inv = 1.f / (sqrtf(var) + LN_EPS);

    float* dst = out + (size_t)row * DMODEL;
    for (int i = tid; i < DMODEL; i += 256)
        dst[i] = (z[i] - mu) * inv * a[i] + bb[i];
}

// ---------------------------------------------------------------------------
extern "C" void kernel_launch(void* const* d_in, const int* in_sizes, int n_in,
                              void* d_out, int out_size)
{
    const float* q      = (const float*)d_in[0];
    const float* w_qs   = (const float*)d_in[1];
    const float* w_ks   = (const float*)d_in[2];
    const float* w_vs   = (const float*)d_in[3];
    const float* proj_w = (const float*)d_in[4];
    const float* proj_b = (const float*)d_in[5];
    const float* ln_a   = (const float*)d_in[6];
    const float* ln_b   = (const float*)d_in[7];
    float* out = (float*)d_out;

    cudaFuncSetAttribute(gemm_mma, cudaFuncAttributeMaxDynamicSharedMemorySize, SM_TOT);
    cudaFuncSetAttribute(attn_mma, cudaFuncAttributeMaxDynamicSharedMemorySize, AT_TOT);

    // QKV: 3 GEMMs [8192,1024]@[1024,1024]; epilogue emits bf16 hi/lo splits
    gemm_mma<<<dim3(64, 8, 3), 256, SM_TOT>>>(q, w_qs, w_ks, w_vs, nullptr, nullptr, 0);
    // Flash attention (HMMA bf16x3)
    attn_mma<<<dim3(SEQ / 128, NHEAD * BATCH), 256, AT_TOT>>>();
    // Output projection + bias + residual
    gemm_mma<<<dim3(64, 8, 1), 256, SM_TOT>>>(nullptr, proj_w, nullptr, nullptr, proj_b, q, 1);
    // LayerNorm
    ln_kernel<<<BL, 256>>>(ln_a, ln_b, out);
}

// round 7
// speedup vs baseline: 3.0993x; 1.3389x over previous
#include <cuda_runtime.h>
#include <cuda_bf16.h>
#include <math.h>
#include <stdint.h>

#define BATCH  4
#define SEQ    2048
#define DMODEL 1024
#define NHEAD  16
#define DK     64
#define BL     (BATCH * SEQ)          // 8192
#define SCALE  (1.0f / 32.0f)         // 1/sqrt(DMODEL)
#define LN_EPS 1e-3f

// ---- scratch (__device__ globals; no allocation allowed) ----
__device__ __nv_bfloat16 g_qAh[BL * DMODEL];     // split of input q
__device__ __nv_bfloat16 g_qAl[BL * DMODEL];
__device__ __nv_bfloat16 g_WQh[DMODEL * DMODEL]; // w_qs transposed+split: [n=h*64+dk][k]
__device__ __nv_bfloat16 g_WQl[DMODEL * DMODEL];
__device__ __nv_bfloat16 g_WKh[DMODEL * DMODEL];
__device__ __nv_bfloat16 g_WKl[DMODEL * DMODEL];
__device__ __nv_bfloat16 g_WVh[DMODEL * DMODEL];
__device__ __nv_bfloat16 g_WVl[DMODEL * DMODEL];
__device__ __nv_bfloat16 g_WPh[DMODEL * DMODEL]; // proj_w split (already [n][k])
__device__ __nv_bfloat16 g_WPl[DMODEL * DMODEL];
__device__ __nv_bfloat16 g_Qh[NHEAD * BL * DK];  // [h*4+b][l][dk], scaled
__device__ __nv_bfloat16 g_Ql[NHEAD * BL * DK];
__device__ __nv_bfloat16 g_Kh[NHEAD * BL * DK];
__device__ __nv_bfloat16 g_Kl[NHEAD * BL * DK];
__device__ __nv_bfloat16 g_Vh[NHEAD * BL * DK];
__device__ __nv_bfloat16 g_Vl[NHEAD * BL * DK];
__device__ __nv_bfloat16 g_Oh[BL * DMODEL];      // attention out, split, concat layout
__device__ __nv_bfloat16 g_Ol[BL * DMODEL];
__device__ float g_P[BL * DMODEL];               // proj + bias + residual

// ===========================================================================
// PTX helpers (baseline PTX — no 'a'-suffix features)
// ===========================================================================
__device__ __forceinline__ uint32_t smem_u32(const void* p) {
    uint32_t a;
    asm("{ .reg .u64 t; cvta.to.shared.u64 t, %1; cvt.u32.u64 %0, t; }" : "=r"(a) : "l"(p));
    return a;
}
__device__ __forceinline__ void ldm4(uint32_t* r, uint32_t addr) {
    asm volatile("ldmatrix.sync.aligned.m8n8.x4.shared.b16 {%0,%1,%2,%3}, [%4];"
        : "=r"(r[0]), "=r"(r[1]), "=r"(r[2]), "=r"(r[3]) : "r"(addr));
}
__device__ __forceinline__ void ldm4t(uint32_t* r, uint32_t addr) {
    asm volatile("ldmatrix.sync.aligned.m8n8.x4.trans.shared.b16 {%0,%1,%2,%3}, [%4];"
        : "=r"(r[0]), "=r"(r[1]), "=r"(r[2]), "=r"(r[3]) : "r"(addr));
}
__device__ __forceinline__ void mma16816(float* c, const uint32_t* a, const uint32_t* b) {
    asm volatile(
        "mma.sync.aligned.m16n8k16.row.col.f32.bf16.bf16.f32 "
        "{%0,%1,%2,%3}, {%4,%5,%6,%7}, {%8,%9}, {%0,%1,%2,%3};"
        : "+f"(c[0]), "+f"(c[1]), "+f"(c[2]), "+f"(c[3])
        : "r"(a[0]), "r"(a[1]), "r"(a[2]), "r"(a[3]), "r"(b[0]), "r"(b[1]));
}
__device__ __forceinline__ void cpa16(uint32_t dst, const void* src) {
    asm volatile("cp.async.cg.shared.global [%0], [%1], 16;" :: "r"(dst), "l"(src));
}
__device__ __forceinline__ void cpa_commit() { asm volatile("cp.async.commit_group;"); }
template<int N> __device__ __forceinline__ void cpa_wait() {
    asm volatile("cp.async.wait_group %0;" :: "n"(N));
}

#define SWZ(off) ((off) ^ (((off) >> 3) & 0x70))

__device__ __forceinline__ void bsplit(float x, __nv_bfloat16& h, __nv_bfloat16& l) {
    h = __float2bfloat16(x);
    l = __float2bfloat16(x - __bfloat162float(h));
}
__device__ __forceinline__ uint32_t pack2(__nv_bfloat16 a, __nv_bfloat16 b) {
    uint16_t ua = *(uint16_t*)&a, ub = *(uint16_t*)&b;
    return (uint32_t)ua | ((uint32_t)ub << 16);
}

// ===========================================================================
// Pre-split kernels
// ===========================================================================
// q [8192][1024] fp32 -> g_qAh/g_qAl
__global__ __launch_bounds__(256) void split_q_kernel(const float* __restrict__ q)
{
    size_t i = ((size_t)blockIdx.x * 256 + threadIdx.x) * 4;
    float4 v = *(const float4*)&q[i];
    __nv_bfloat16 h0, h1, h2, h3, l0, l1, l2, l3;
    bsplit(v.x, h0, l0); bsplit(v.y, h1, l1);
    bsplit(v.z, h2, l2); bsplit(v.w, h3, l3);
    *(uint2*)&g_qAh[i] = make_uint2(pack2(h0, h1), pack2(h2, h3));
    *(uint2*)&g_qAl[i] = make_uint2(pack2(l0, l1), pack2(l2, l3));
}

// w[h][k][dk] -> B[n=h*64+dk][k], split.  grid (16 k-tiles, 16 h, 3 mats)
__global__ __launch_bounds__(256) void split_wt_kernel(
    const float* __restrict__ w0, const float* __restrict__ w1, const float* __restrict__ w2)
{
    const float* w;
    __nv_bfloat16 *Bh, *Bl;
    if (blockIdx.z == 0)      { w = w0; Bh = g_WQh; Bl = g_WQl; }
    else if (blockIdx.z == 1) { w = w1; Bh = g_WKh; Bl = g_WKl; }
    else                      { w = w2; Bh = g_WVh; Bl = g_WVl; }
    const int h = blockIdx.y, k0 = blockIdx.x * 64;
    __shared__ float t[64][65];
    const int tid = threadIdx.x;
    #pragma unroll
    for (int i = 0; i < 16; i++) {
        int e = i * 256 + tid;
        int k = e >> 6, dk = e & 63;
        t[k][dk] = w[(size_t)h * 65536 + (size_t)(k0 + k) * 64 + dk];
    }
    __syncthreads();
    #pragma unroll
    for (int i = 0; i < 16; i++) {
        int e = i * 256 + tid;
        int dk = e >> 6, k = e & 63;
        __nv_bfloat16 hh, ll;
        bsplit(t[k][dk], hh, ll);
        size_t o = (size_t)(h * 64 + dk) * 1024 + k0 + k;
        Bh[o] = hh; Bl[o] = ll;
    }
}

// proj_w [n][k] elementwise split
__global__ __launch_bounds__(256) void split_w_kernel(const float* __restrict__ w)
{
    size_t i = ((size_t)blockIdx.x * 256 + threadIdx.x) * 4;
    float4 v = *(const float4*)&w[i];
    __nv_bfloat16 h0, h1, h2, h3, l0, l1, l2, l3;
    bsplit(v.x, h0, l0); bsplit(v.y, h1, l1);
    bsplit(v.z, h2, l2); bsplit(v.w, h3, l3);
    *(uint2*)&g_WPh[i] = make_uint2(pack2(h0, h1), pack2(h2, h3));
    *(uint2*)&g_WPl[i] = make_uint2(pack2(l0, l1), pack2(l2, l3));
}

// ===========================================================================
// bf16x3 GEMM, pre-split inputs, cp.async double-buffered.
// C[8192,1024] = A @ B^T; tile 128x128, k-chunk 64, 8 warps of 64x32.
// mode 0 (z=0,1,2): A=g_qA*, B=g_WQ/K/V*; epilogue scatter split to g_Q/K/V*
// mode 1: A=g_O*, B=g_WP*; epilogue fp32 + bias + residual -> g_P
// ===========================================================================
#define GS_AH 0
#define GS_AL 16384
#define GS_BH 32768
#define GS_BL 49152
#define GS_STAGE 65536
#define GS_TOT   131072

__global__ __launch_bounds__(256) void gemm_bf16(
    const float* __restrict__ bias,
    const float* __restrict__ resid,
    int mode)
{
    extern __shared__ char sm[];
    const uint32_t smb = smem_u32(sm);
    const int tid  = threadIdx.x;
    const int lane = tid & 31, wid = tid >> 5;
    const int wm = wid >> 2, wn = wid & 3;
    const int n0   = blockIdx.x * 128;   // x = ntile (fast) -> A row-tile L2 reuse
    const int row0 = blockIdx.y * 128;

    const __nv_bfloat16 *Ah, *Al, *Bh, *Bl;
    __nv_bfloat16 *SpH = nullptr, *SpL = nullptr;
    float sc = 1.0f;
    if (mode == 0) {
        Ah = g_qAh; Al = g_qAl;
        if (blockIdx.z == 0)      { Bh = g_WQh; Bl = g_WQl; SpH = g_Qh; SpL = g_Ql; sc = SCALE; }
        else if (blockIdx.z == 1) { Bh = g_WKh; Bl = g_WKl; SpH = g_Kh; SpL = g_Kl; }
        else                      { Bh = g_WVh; Bl = g_WVl; SpH = g_Vh; SpL = g_Vl; }
    } else {
        Ah = g_Oh; Al = g_Ol; Bh = g_WPh; Bl = g_WPl;
    }

    const int grp = lane >> 3, rr = lane & 7;
    const uint32_t swx = (uint32_t)(rr << 4);
    const int arowb = wm * 64 + (grp & 1) * 8 + rr;
    const int akb   = (grp >> 1) * 16;
    const int bnb   = wn * 32 + ((grp >> 1) & 1) * 8 + rr;
    const int bkb   = (grp & 1) * 16;

    float acc[4][4][4];
    #pragma unroll
    for (int i = 0; i < 4; i++)
        #pragma unroll
        for (int j = 0; j < 4; j++)
            #pragma unroll
            for (int t = 0; t < 4; t++) acc[i][j][t] = 0.f;

    // cp.async staging: 1024 granules per array per stage, 4/thread
    #define G_ISSUE(kt, stg) do {                                                  \
        int kk0 = (kt) * 64;                                                       \
        _Pragma("unroll")                                                          \
        for (int i = 0; i < 4; i++) {                                              \
            int g = i * 256 + tid;                                                 \
            int r = g >> 3, c = g & 7;                                             \
            uint32_t d = (stg) + (uint32_t)(r * 128 + ((c * 16) ^ ((r & 7) << 4)));\
            size_t sa = (size_t)(row0 + r) * 1024 + kk0 + c * 8;                   \
            size_t sb = (size_t)(n0 + r) * 1024 + kk0 + c * 8;                     \
            cpa16(d + GS_AH, &Ah[sa]); cpa16(d + GS_AL, &Al[sa]);                  \
            cpa16(d + GS_BH, &Bh[sb]); cpa16(d + GS_BL, &Bl[sb]);                  \
        }                                                                          \
    } while (0)

    G_ISSUE(0, smb);
    cpa_commit();

    for (int kt = 0; kt < 16; kt++) {
        uint32_t stg = smb + (uint32_t)((kt & 1) * GS_STAGE);
        if (kt < 15) {
            G_ISSUE(kt + 1, smb + (uint32_t)(((kt + 1) & 1) * GS_STAGE));
            cpa_commit();
            cpa_wait<1>();
        } else {
            cpa_wait<0>();
        }
        __syncthreads();

        #pragma unroll
        for (int ks = 0; ks < 4; ks++) {
            uint32_t bh[4][2], bl[4][2];
            #pragma unroll
            for (int pr = 0; pr < 2; pr++) {
                int brow = bnb + pr * 16;
                uint32_t boff = (uint32_t)(brow * 128) + (((uint32_t)(ks * 32 + bkb)) ^ swx);
                uint32_t r4[4];
                ldm4(r4, stg + GS_BH + boff);
                bh[pr*2][0] = r4[0]; bh[pr*2][1] = r4[1];
                bh[pr*2+1][0] = r4[2]; bh[pr*2+1][1] = r4[3];
                ldm4(r4, stg + GS_BL + boff);
                bl[pr*2][0] = r4[0]; bl[pr*2][1] = r4[1];
                bl[pr*2+1][0] = r4[2]; bl[pr*2+1][1] = r4[3];
            }
            #pragma unroll
            for (int mt = 0; mt < 4; mt++) {
                int arow = arowb + mt * 16;
                uint32_t aoff = (uint32_t)(arow * 128) + (((uint32_t)(ks * 32 + akb)) ^ swx);
                uint32_t ah[4], al[4];
                ldm4(ah, stg + GS_AH + aoff);
                ldm4(al, stg + GS_AL + aoff);
                #pragma unroll
                for (int nt = 0; nt < 4; nt++) {
                    mma16816(acc[mt][nt], ah, bh[nt]);
                    mma16816(acc[mt][nt], ah, bl[nt]);
                    mma16816(acc[mt][nt], al, bh[nt]);
                }
            }
        }
        __syncthreads();
    }

    // ---- epilogue ----
    const int l4 = lane >> 2, lm = lane & 3;
    #pragma unroll
    for (int mt = 0; mt < 4; mt++) {
        #pragma unroll
        for (int nt = 0; nt < 4; nt++) {
            int m = row0 + wm * 64 + mt * 16 + l4;
            int n = n0 + wn * 32 + nt * 8 + lm * 2;
            if (mode == 0) {
                int hh = n >> 6, dk = n & 63;
                float v0 = acc[mt][nt][0] * sc, v1 = acc[mt][nt][1] * sc;
                float v2 = acc[mt][nt][2] * sc, v3 = acc[mt][nt][3] * sc;
                __nv_bfloat16 h0, h1, h2, h3, L0, L1, L2, L3;
                bsplit(v0, h0, L0); bsplit(v1, h1, L1);
                bsplit(v2, h2, L2); bsplit(v3, h3, L3);
                int b0_ = m >> 11, l0_ = m & 2047;
                size_t i0 = (((size_t)(hh * 4 + b0_)) * 2048 + l0_) * 64 + dk;
                *(uint32_t*)&SpH[i0] = pack2(h0, h1);
                *(uint32_t*)&SpL[i0] = pack2(L0, L1);
                int m2 = m + 8;
                int b1_ = m2 >> 11, l1_ = m2 & 2047;
                size_t i1 = (((size_t)(hh * 4 + b1_)) * 2048 + l1_) * 64 + dk;
                *(uint32_t*)&SpH[i1] = pack2(h2, h3);
                *(uint32_t*)&SpL[i1] = pack2(L2, L3);
            } else {
                float2 bv = *(const float2*)&bias[n];
                float2 r0v = *(const float2*)&resid[(size_t)m * 1024 + n];
                float2 r1v = *(const float2*)&resid[(size_t)(m + 8) * 1024 + n];
                *(float2*)&g_P[(size_t)m * 1024 + n] =
                    make_float2(acc[mt][nt][0] + bv.x + r0v.x, acc[mt][nt][1] + bv.y + r0v.y);
                *(float2*)&g_P[(size_t)(m + 8) * 1024 + n] =
                    make_float2(acc[mt][nt][2] + bv.x + r1v.x, acc[mt][nt][3] + bv.y + r1v.y);
            }
        }
    }
}

// ===========================================================================
// Flash attention, HMMA bf16x3 (unchanged mainloop; epilogue emits split bf16)
// ===========================================================================
#define AT_STAGE 32768   // KH 0 | KL 8192 | VH 16384 | VL 24576
#define AT_TOT   65536

__global__ __launch_bounds__(256) void attn_mma()
{
    extern __shared__ char sm[];
    const uint32_t smb = smem_u32(sm);
    const int tid = threadIdx.x, lane = tid & 31, wid = tid >> 5;
    const int h = blockIdx.y >> 2, b = blockIdx.y & 3;
    const size_t base = (size_t)(h * BATCH + b) * SEQ * DK;
    const __nv_bfloat16* Qh = g_Qh + base;
    const __nv_bfloat16* Ql = g_Ql + base;
    const __nv_bfloat16* Kh = g_Kh + base;
    const __nv_bfloat16* Kl = g_Kl + base;
    const __nv_bfloat16* Vh = g_Vh + base;
    const __nv_bfloat16* Vl = g_Vl + base;
    const int q0 = blockIdx.x * 128;

    const int grp = lane >> 3, rr = lane & 7;
    const uint32_t swx = (uint32_t)(rr << 4);

    uint32_t qha[4][4], qla[4][4];
    const uint32_t qaoff_base = (uint32_t)((wid * 16 + (grp & 1) * 8 + rr) * 128);
    #pragma unroll
    for (int ph = 0; ph < 2; ph++) {
        const __nv_bfloat16* Qs = ph ? Ql : Qh;
        #pragma unroll
        for (int i = 0; i < 4; i++) {
            int g = i * 256 + tid;
            int r = g >> 3, c = g & 7;
            uint4 v = *(const uint4*)&Qs[(size_t)(q0 + r) * DK + c * 8];
            *(uint4*)(sm + (r * 128 + ((c * 16) ^ ((r & 7) << 4)))) = v;
        }
        __syncthreads();
        #pragma unroll
        for (int ks = 0; ks < 4; ks++) {
            uint32_t aoff = qaoff_base + (((uint32_t)(ks * 32 + (grp >> 1) * 16)) ^ swx);
            if (ph == 0) ldm4(qha[ks], smb + aoff);
            else         ldm4(qla[ks], smb + aoff);
        }
        __syncthreads();
    }

    float o[8][4];
    #pragma unroll
    for (int i = 0; i < 8; i++)
        #pragma unroll
        for (int j = 0; j < 4; j++) o[i][j] = 0.f;
    float m0 = -1e30f, m1 = -1e30f, l0 = 0.f, l1 = 0.f;

    const int lg0 = tid, lg1 = tid + 256;
    #define ISSUE_TILE(kv0, stg) do {                                           \
        int rA = lg0 >> 3, cA = lg0 & 7;                                        \
        uint32_t dA = (stg) + (uint32_t)(rA * 128 + ((cA * 16) ^ ((rA & 7) << 4))); \
        size_t sA = (size_t)((kv0) + rA) * DK + cA * 8;                         \
        cpa16(dA,          &Kh[sA]); cpa16(dA + 8192,  &Kl[sA]);                \
        cpa16(dA + 16384,  &Vh[sA]); cpa16(dA + 24576, &Vl[sA]);                \
        int rB = lg1 >> 3, cB = lg1 & 7;                                        \
        uint32_t dB = (stg) + (uint32_t)(rB * 128 + ((cB * 16) ^ ((rB & 7) << 4))); \
        size_t sB = (size_t)((kv0) + rB) * DK + cB * 8;                         \
        cpa16(dB,          &Kh[sB]); cpa16(dB + 8192,  &Kl[sB]);                \
        cpa16(dB + 16384,  &Vh[sB]); cpa16(dB + 24576, &Vl[sB]);                \
    } while (0)

    ISSUE_TILE(0, smb);
    cpa_commit();

    const uint32_t kboff_base = (uint32_t)((((grp >> 1) & 1) * 8 + rr) * 128);
    const int vkey = lane & 15, vdvb = (lane >> 4) * 8;

    for (int t = 0; t < 32; t++) {
        uint32_t stg = smb + (uint32_t)((t & 1) * AT_STAGE);
        if (t < 31) {
            ISSUE_TILE((t + 1) * 64, smb + (uint32_t)(((t + 1) & 1) * AT_STAGE));
            cpa_commit();
            cpa_wait<1>();
        } else {
            cpa_wait<0>();
        }
        __syncthreads();

        float s[8][4];
        #pragma unroll
        for (int i = 0; i < 8; i++)
            #pragma unroll
            for (int j = 0; j < 4; j++) s[i][j] = 0.f;

        #pragma unroll
        for (int ks = 0; ks < 4; ks++) {
            #pragma unroll
            for (int pr = 0; pr < 4; pr++) {
                uint32_t boff = (uint32_t)(pr * 16 * 128) + kboff_base
                              + (((uint32_t)(ks * 32 + (grp & 1) * 16)) ^ swx);
                uint32_t kh4[4], kl4[4];
                ldm4(kh4, stg + boff);
                ldm4(kl4, stg + 8192 + boff);
                mma16816(s[2*pr],   qha[ks], kh4);
                mma16816(s[2*pr+1], qha[ks], kh4 + 2);
                mma16816(s[2*pr],   qha[ks], kl4);
                mma16816(s[2*pr+1], qha[ks], kl4 + 2);
                mma16816(s[2*pr],   qla[ks], kh4);
                mma16816(s[2*pr+1], qla[ks], kh4 + 2);
            }
        }

        float a0 = -1e30f, a1 = -1e30f;
        #pragma unroll
        for (int nt = 0; nt < 8; nt++) {
            a0 = fmaxf(a0, fmaxf(s[nt][0], s[nt][1]));
            a1 = fmaxf(a1, fmaxf(s[nt][2], s[nt][3]));
        }
        a0 = fmaxf(a0, __shfl_xor_sync(0xffffffffu, a0, 1));
        a0 = fmaxf(a0, __shfl_xor_sync(0xffffffffu, a0, 2));
        a1 = fmaxf(a1, __shfl_xor_sync(0xffffffffu, a1, 1));
        a1 = fmaxf(a1, __shfl_xor_sync(0xffffffffu, a1, 2));
        float nm0 = fmaxf(m0, a0), nm1 = fmaxf(m1, a1);
        float alpha0 = __expf(m0 - nm0), alpha1 = __expf(m1 - nm1);
        m0 = nm0; m1 = nm1;

        float rs0 = 0.f, rs1 = 0.f;
        #pragma unroll
        for (int nt = 0; nt < 8; nt++) {
            s[nt][0] = __expf(s[nt][0] - nm0); rs0 += s[nt][0];
            s[nt][1] = __expf(s[nt][1] - nm0); rs0 += s[nt][1];
            s[nt][2] = __expf(s[nt][2] - nm1); rs1 += s[nt][2];
            s[nt][3] = __expf(s[nt][3] - nm1); rs1 += s[nt][3];
        }
        rs0 += __shfl_xor_sync(0xffffffffu, rs0, 1);
        rs0 += __shfl_xor_sync(0xffffffffu, rs0, 2);
        rs1 += __shfl_xor_sync(0xffffffffu, rs1, 1);
        rs1 += __shfl_xor_sync(0xffffffffu, rs1, 2);
        l0 = l0 * alpha0 + rs0;
        l1 = l1 * alpha1 + rs1;
        #pragma unroll
        for (int nt = 0; nt < 8; nt++) {
            o[nt][0] *= alpha0; o[nt][1] *= alpha0;
            o[nt][2] *= alpha1; o[nt][3] *= alpha1;
        }

        uint32_t pah[4][4], pal[4][4];
        #pragma unroll
        for (int ss = 0; ss < 4; ss++) {
            __nv_bfloat16 h0, h1, L0, L1;
            bsplit(s[2*ss][0], h0, L0); bsplit(s[2*ss][1], h1, L1);
            pah[ss][0] = pack2(h0, h1); pal[ss][0] = pack2(L0, L1);
            bsplit(s[2*ss][2], h0, L0); bsplit(s[2*ss][3], h1, L1);
            pah[ss][1] = pack2(h0, h1); pal[ss][1] = pack2(L0, L1);
            bsplit(s[2*ss+1][0], h0, L0); bsplit(s[2*ss+1][1], h1, L1);
            pah[ss][2] = pack2(h0, h1); pal[ss][2] = pack2(L0, L1);
            bsplit(s[2*ss+1][2], h0, L0); bsplit(s[2*ss+1][3], h1, L1);
            pah[ss][3] = pack2(h0, h1); pal[ss][3] = pack2(L0, L1);
        }

        #pragma unroll
        for (int ss = 0; ss < 4; ss++) {
            #pragma unroll
            for (int dp = 0; dp < 4; dp++) {
                int key = ss * 16 + vkey;
                int dvc = dp * 16 + vdvb;
                uint32_t voff = (uint32_t)(key * 128 + ((dvc * 2) ^ ((key & 7) << 4)));
                uint32_t vh4[4], vl4[4];
                ldm4t(vh4, stg + 16384 + voff);
                ldm4t(vl4, stg + 24576 + voff);
                mma16816(o[2*dp],   pah[ss], vh4);
                mma16816(o[2*dp+1], pah[ss], vh4 + 2);
                mma16816(o[2*dp],   pah[ss], vl4);
                mma16816(o[2*dp+1], pah[ss], vl4 + 2);
                mma16816(o[2*dp],   pal[ss], vh4);
                mma16816(o[2*dp+1], pal[ss], vh4 + 2);
            }
        }
        __syncthreads();
    }

    // ---- epilogue: O /= l, split to bf16 hi/lo, concat layout ----
    float il0 = 1.f / l0, il1 = 1.f / l1;
    int r0_ = q0 + wid * 16 + (lane >> 2);
    __nv_bfloat16* OhG = g_Oh + (size_t)b * SEQ * DMODEL + h * 64;
    __nv_bfloat16* OlG = g_Ol + (size_t)b * SEQ * DMODEL + h * 64;
    #pragma unroll
    for (int nt = 0; nt < 8; nt++) {
        int dv = nt * 8 + (lane & 3) * 2;
        __nv_bfloat16 h0, h1, L0, L1;
        bsplit(o[nt][0] * il0, h0, L0); bsplit(o[nt][1] * il0, h1, L1);
        *(uint32_t*)&OhG[(size_t)r0_ * DMODEL + dv] = pack2(h0, h1);
        *(uint32_t*)&OlG[(size_t)r0_ * DMODEL + dv] = pack2(L0, L1);
        bsplit(o[nt][2] * il1, h0, L0); bsplit(o[nt][3] * il1, h1, L1);
        *(uint32_t*)&OhG[(size_t)(r0_ + 8) * DMODEL + dv] = pack2(h0, h1);
        *(uint32_t*)&OlG[(size_t)(r0_ + 8) * DMODEL + dv] = pack2(L0, L1);
    }
}

// ---------------------------------------------------------------------------
// LayerNorm (ddof=1; divide by sigma + eps), one block/row
// ---------------------------------------------------------------------------
__device__ __forceinline__ float blk_sum256(float v, float* red)
{
    #pragma unroll
    for (int o = 16; o; o >>= 1) v += __shfl_xor_sync(0xffffffffu, v, o);
    __syncthreads();
    if ((threadIdx.x & 31) == 0) red[threadIdx.x >> 5] = v;
    __syncthreads();
    if (threadIdx.x < 32) {
        float t = (threadIdx.x < 8) ? red[threadIdx.x] : 0.f;
        #pragma unroll
        for (int o = 4; o; o >>= 1) t += __shfl_xor_sync(0xffffffffu, t, o);
        if (threadIdx.x == 0) red[0] = t;
    }
    __syncthreads();
    return red[0];
}

__global__ __launch_bounds__(256) void ln_kernel(
    const float* __restrict__ a,
    const float* __restrict__ bb,
    float* __restrict__ out)
{
    __shared__ float z[DMODEL];
    __shared__ float red[8];
    const int row = blockIdx.x;
    const int tid = threadIdx.x;
    const float* src = g_P + (size_t)row * DMODEL;

    float ls = 0.f;
    for (int i = tid; i < DMODEL; i += 256) { float v = src[i]; z[i] = v; ls += v; }
    float mu = blk_sum256(ls, red) * (1.0f / DMODEL);

    float ls2 = 0.f;
    for (int i = tid; i < DMODEL; i += 256) { float d = z[i] - mu; ls2 += d * d; }
    float var = blk_sum256(ls2, red) * (1.0f / (DMODEL - 1));
    float inv = 1.f / (sqrtf(var) + LN_EPS);

    float* dst = out + (size_t)row * DMODEL;
    for (int i = tid; i < DMODEL; i += 256)
        dst[i] = (z[i] - mu) * inv * a[i] + bb[i];
}

// ---------------------------------------------------------------------------
extern "C" void kernel_launch(void* const* d_in, const int* in_sizes, int n_in,
                              void* d_out, int out_size)
{
    const float* q      = (const float*)d_in[0];
    const float* w_qs   = (const float*)d_in[1];
    const float* w_ks   = (const float*)d_in[2];
    const float* w_vs   = (const float*)d_in[3];
    const float* proj_w = (const float*)d_in[4];
    const float* proj_b = (const float*)d_in[5];
    const float* ln_a   = (const float*)d_in[6];
    const float* ln_b   = (const float*)d_in[7];
    float* out = (float*)d_out;

    cudaFuncSetAttribute(gemm_bf16, cudaFuncAttributeMaxDynamicSharedMemorySize, GS_TOT);
    cudaFuncSetAttribute(attn_mma, cudaFuncAttributeMaxDynamicSharedMemorySize, AT_TOT);

    // pre-split inputs/weights to bf16 hi/lo
    split_q_kernel<<<BL * DMODEL / 1024, 256>>>(q);
    split_wt_kernel<<<dim3(16, 16, 3), 256>>>(w_qs, w_ks, w_vs);
    split_w_kernel<<<DMODEL * DMODEL / 1024, 256>>>(proj_w);

    // QKV GEMMs (heads folded into N)
    gemm_bf16<<<dim3(8, 64, 3), 256, GS_TOT>>>(nullptr, nullptr, 0);
    // Flash attention (HMMA bf16x3)
    attn_mma<<<dim3(SEQ / 128, NHEAD * BATCH), 256, AT_TOT>>>();
    // Output projection + bias + residual
    gemm_bf16<<<dim3(8, 64, 1), 256, GS_TOT>>>(proj_b, q, 1);
    // LayerNorm
    ln_kernel<<<BL, 256>>>(ln_a, ln_b, out);
}